// round 15
// baseline (speedup 1.0000x reference)
#include <cuda_runtime.h>
#include <cuda_fp16.h>
#include <stdint.h>
#include <math.h>

#define NODES_MAX 100000
#define M_PAD     100096
#define EDGES_MAX 1600000
#define IN_F 256
#define HID 128
#define OUTF 64
#define FILLB 512          // fill blocks prepended to the L1 GEMM grid

// ---------------- scratch (static __device__, no allocs) ----------------
__device__ __half  g_bufA[(size_t)M_PAD * HID];
__device__ __half  g_bufB[(size_t)M_PAD * HID];
__device__ __half  g_aggM[(size_t)M_PAD * HID];
__device__ __half  g_aggV[(size_t)M_PAD * HID];
__device__ float   g_norm1[M_PAD];
__device__ float   g_norm2[M_PAD];
__device__ int     g_deg[NODES_MAX];
__device__ int     g_cursor[NODES_MAX];
__device__ int     g_offs[NODES_MAX + 1];
__device__ int     g_csr[EDGES_MAX];
__device__ int     g_bsum[128];
__device__ int     g_flag[128];
// fp16 weights, packed as k-pair half2: [mat][K/2][N]
__device__ __half2 g_w1[2 * 128 * 128];
__device__ __half2 g_w2[2 * 64 * 64];

// ---------------- init: zero counters/flags + weight fp16 pack ----------------
__global__ void k_init(const float* __restrict__ Wm1, const float* __restrict__ Wv1,
                       const float* __restrict__ Wm2, const float* __restrict__ Wv2, int n) {
    int i = blockIdx.x * blockDim.x + threadIdx.x;
    if (i < n) { g_deg[i] = 0; g_cursor[i] = 0; }
    if (i < 128) g_flag[i] = 0;
    if (i < 2 * 128 * 128) {
        int mat = i >> 14;
        int rem = i & 16383;
        int kk = rem >> 7;
        int nn = rem & 127;
        const float* W = mat ? Wv1 : Wm1;
        g_w1[i] = __floats2half2_rn(W[(2 * kk) * HID + nn], W[(2 * kk + 1) * HID + nn]);
    }
    if (i < 2 * 64 * 64) {
        int mat = i >> 12;
        int rem = i & 4095;
        int kk = rem >> 6;
        int nn = rem & 63;
        const float* W = mat ? Wv2 : Wm2;
        g_w2[i] = __floats2half2_rn(W[(2 * kk) * OUTF + nn], W[(2 * kk + 1) * OUTF + nn]);
    }
}

__global__ void k_count(const int* __restrict__ dst, int E) {
    int e = blockIdx.x * blockDim.x + threadIdx.x;
    if (e < E) atomicAdd(&g_deg[dst[e]], 1);
}

// ---------------- single-pass scan (+ fused norms), chained lookback ----------------
__global__ void k_scan(int n, int nb) {
    __shared__ int sm[1024];
    __shared__ int soff;
    int t = threadIdx.x;
    int bid = blockIdx.x;
    int i = bid * 1024 + t;
    int v = (i < n) ? g_deg[i] : 0;
    if (i < n) {
        float d = fmaxf((float)v, 1.0f);
        float n1 = 1.0f / sqrtf(d);
        g_norm1[i] = n1;
        g_norm2[i] = n1 * n1;
    }
    sm[t] = v;
    __syncthreads();
#pragma unroll
    for (int d = 1; d < 1024; d <<= 1) {
        int u = (t >= d) ? sm[t - d] : 0;
        __syncthreads();
        sm[t] += u;
        __syncthreads();
    }
    if (t == 1023) {
        g_bsum[bid] = sm[1023];
        __threadfence();
        atomicExch(&g_flag[bid], 1);
    }
    int acc = 0;
    for (int b = t; b < bid; b += 1024) {
        while (atomicAdd(&g_flag[b], 0) == 0) {}
        acc += g_bsum[b];
    }
#pragma unroll
    for (int o = 16; o; o >>= 1) acc += __shfl_down_sync(0xFFFFFFFFu, acc, o);
    __shared__ int sw[32];
    if ((t & 31) == 0) sw[t >> 5] = acc;
    __syncthreads();
    if (t < 32) {
        int vv = sw[t];
#pragma unroll
        for (int o = 16; o; o >>= 1) vv += __shfl_down_sync(0xFFFFFFFFu, vv, o);
        if (t == 0) soff = vv;
    }
    __syncthreads();
    int off = soff;
    if (i < n) g_offs[i] = off + sm[t] - v;
    if (bid == nb - 1 && t == 1023) g_offs[n] = off + sm[1023];
}

// ================= tensor-core helpers =================
__device__ __forceinline__ void mma_f16(float* d, uint32_t a0, uint32_t a1,
                                        uint32_t a2, uint32_t a3,
                                        uint32_t b0, uint32_t b1) {
    asm volatile(
        "mma.sync.aligned.m16n8k16.row.col.f32.f16.f16.f32 "
        "{%0,%1,%2,%3},{%4,%5,%6,%7},{%8,%9},{%0,%1,%2,%3};"
        : "+f"(d[0]), "+f"(d[1]), "+f"(d[2]), "+f"(d[3])
        : "r"(a0), "r"(a1), "r"(a2), "r"(a3), "r"(b0), "r"(b1));
}

__device__ __forceinline__ void cp16(uint32_t dst, const void* src, int sz) {
    asm volatile("cp.async.cg.shared.global [%0], [%1], 16, %2;"
                 :: "r"(dst), "l"(src), "r"(sz));
}
__device__ __forceinline__ void cp_commit() {
    asm volatile("cp.async.commit_group;");
}
template <int N> __device__ __forceinline__ void cp_wait() {
    asm volatile("cp.async.wait_group %0;" :: "n"(N));
}

#define APAD 20      // floats per A smem row (16 + 4)
#define BPAD2 136    // half2 words per B pair-row (128 + 8)   [L2]
#define BPAD2N 264   // half2 words per B pair-row (256 + 8)   [L1]
#define A2PAD 24     // halfs per A smem row (16 + 8)   [L2 fp16 A]

// ================= FUSED: CSR fill (blocks 0..FILLB-1) + layer-1 GEMM =================
// GEMM: BM=32 x 256 out-cols (2 mats x 128), 8 warps: warp_m(2) x16 rows, warp_n(4) x32 cols.
// Small tile -> 32 acc regs/thread -> 3 CTAs/SM (24 warps) for latency hiding.
__global__ void __launch_bounds__(256, 3)
k_l1_fused(const float* __restrict__ X,
           const float* __restrict__ bm, const float* __restrict__ bv,
           __half* __restrict__ Cm, __half* __restrict__ Cv, int M,
           const int* __restrict__ src, const int* __restrict__ dst, int E) {
    // ---- fill blocks ----
    if (blockIdx.x < FILLB) {
        const int stride = FILLB * 256;
        for (int e = blockIdx.x * 256 + threadIdx.x; e < E; e += stride) {
            int d = dst[e];
            int p = atomicAdd(&g_cursor[d], 1);
            g_csr[g_offs[d] + p] = src[e];
        }
        return;
    }

    // ---- GEMM blocks ----
    __shared__ float    As[2][32 * APAD];
    __shared__ uint32_t Bh[2][8 * BPAD2N];

    const int tid = threadIdx.x;
    const int lane = tid & 31;
    const int wid = tid >> 5;
    const int warp_m = wid & 1;       // 2 bands of 16 rows
    const int warp_n = wid >> 1;      // 4 bands of 32 cols
    const int gid = lane >> 2;
    const int tig = lane & 3;
    const int bm_base = (blockIdx.x - FILLB) * 32;

    float acc[2][4][4];   // [matrix][nt][reg]  (single 16-row M-tile)
#pragma unroll
    for (int a = 0; a < 2; a++)
#pragma unroll
        for (int c = 0; c < 4; c++)
#pragma unroll
            for (int d = 0; d < 4; d++) acc[a][c][d] = 0.f;

    uint32_t asb[2], bhb[2];
#pragma unroll
    for (int s = 0; s < 2; s++) {
        asb[s] = (uint32_t)__cvta_generic_to_shared(&As[s][0]);
        bhb[s] = (uint32_t)__cvta_generic_to_shared(&Bh[s][0]);
    }

    auto issue = [&](int stage, int k0) {
        int kk0 = k0 >> 1;
        // A tile: 32 rows x 16 k fp32 = 128 x 16B (threads 0..127)
        if (tid < 128) {
            int r = tid >> 2, kq = tid & 3;
            int gm = bm_base + r;
            int ok = (gm < M) ? 16 : 0;
            const float* srca = X + (size_t)min(gm, M - 1) * IN_F + k0 + kq * 4;
            cp16(asb[stage] + (uint32_t)(r * APAD + kq * 4) * 4, srca, ok);
        }
        // B tile: 2 mat x 8 prows x 32 chunks = 512 x 16B (2 chunks/thread)
#pragma unroll
        for (int c = tid; c < 512; c += 256) {
            int mat = c >> 8;
            int pr = (c >> 5) & 7;
            int q = c & 31;
            const __half2* srcb = g_w1 + ((mat * 128 + kk0 + pr) * 128 + q * 4);
            uint32_t dstb = bhb[stage] + (uint32_t)(pr * BPAD2N + mat * 128 + q * 4) * 4;
            cp16(dstb, srcb, 16);
        }
        cp_commit();
    };

    issue(0, 0);

    const int NITER = IN_F / 16;   // 16
    for (int it = 0; it < NITER; it++) {
        int stage = it & 1;
        if (it + 1 < NITER) {
            issue(stage ^ 1, (it + 1) * 16);
            cp_wait<1>();
        } else {
            cp_wait<0>();
        }
        __syncthreads();

        const float* as = As[stage];
        const uint32_t* bh = Bh[stage];

        // A fragment: 16 rows x k16, fp32 -> fp16
        uint32_t ahi[4];
        {
            int rb = warp_m * 16;
            const float* r0 = as + (rb + gid) * APAD;
            const float* r1 = as + (rb + gid + 8) * APAD;
            float2 x0 = *reinterpret_cast<const float2*>(r0 + 2 * tig);
            float2 x1 = *reinterpret_cast<const float2*>(r1 + 2 * tig);
            float2 x2 = *reinterpret_cast<const float2*>(r0 + 2 * tig + 8);
            float2 x3 = *reinterpret_cast<const float2*>(r1 + 2 * tig + 8);
            __half2 h;
            h = __floats2half2_rn(x0.x, x0.y); ahi[0] = *reinterpret_cast<uint32_t*>(&h);
            h = __floats2half2_rn(x1.x, x1.y); ahi[1] = *reinterpret_cast<uint32_t*>(&h);
            h = __floats2half2_rn(x2.x, x2.y); ahi[2] = *reinterpret_cast<uint32_t*>(&h);
            h = __floats2half2_rn(x3.x, x3.y); ahi[3] = *reinterpret_cast<uint32_t*>(&h);
        }

#pragma unroll
        for (int mat = 0; mat < 2; mat++) {
#pragma unroll
            for (int nt = 0; nt < 4; nt++) {
                int col = mat * 128 + warp_n * 32 + nt * 8 + gid;
                uint32_t bh0 = bh[tig * BPAD2N + col];
                uint32_t bh1 = bh[(tig + 4) * BPAD2N + col];
                mma_f16(acc[mat][nt], ahi[0], ahi[1], ahi[2], ahi[3], bh0, bh1);
            }
        }
        __syncthreads();
    }

    // ---- epilogue: bias + relu + att + norms -> fp16 messages ----
#pragma unroll
    for (int nt = 0; nt < 4; nt++) {
        int gc = warp_n * 32 + nt * 8 + tig * 2;
        float bm0 = bm[gc], bm1 = bm[gc + 1];
        float bv0 = bv[gc], bv1 = bv[gc + 1];
#pragma unroll
        for (int half = 0; half < 2; half++) {
            int gm = bm_base + warp_m * 16 + gid + half * 8;
            if (gm >= M) continue;
            float n1 = g_norm1[gm];
            float n2 = g_norm2[gm];
            float mean0 = fmaxf(acc[0][nt][half * 2 + 0] + bm0, 0.f);
            float mean1 = fmaxf(acc[0][nt][half * 2 + 1] + bm1, 0.f);
            float var0  = fmaxf(acc[1][nt][half * 2 + 0] + bv0, 0.f);
            float var1  = fmaxf(acc[1][nt][half * 2 + 1] + bv1, 0.f);
            float att0 = expf(-var0), att1 = expf(-var1);
            float2 om = make_float2(mean0 * att0 * n1, mean1 * att1 * n1);
            float2 ov = make_float2(var0 * att0 * att0 * n2, var1 * att1 * att1 * n2);
            *reinterpret_cast<__half2*>(Cm + (size_t)gm * HID + gc) = __float22half2_rn(om);
            *reinterpret_cast<__half2*>(Cv + (size_t)gm * HID + gc) = __float22half2_rn(ov);
        }
    }
}

// ================= layer-2: dual-A (fp16) GEMM, 1-term, fp16 weights =================
__global__ void __launch_bounds__(256)
k_l2_f16(const __half* __restrict__ Am, const __half* __restrict__ Av,
         const float* __restrict__ bm, const float* __restrict__ bv,
         __half* __restrict__ Cm, __half* __restrict__ Cv) {
    __shared__ __half   As[2][2][128 * A2PAD];
    __shared__ uint32_t Bh[2][8 * BPAD2];

    const int tid = threadIdx.x;
    const int lane = tid & 31;
    const int wid = tid >> 5;
    const int warp_m = wid & 3;
    const int warp_n = wid >> 2;
    const int gid = lane >> 2;
    const int tig = lane & 3;
    const int bm_base = blockIdx.x * 128;

    float acc[2][2][4][4];
#pragma unroll
    for (int a = 0; a < 2; a++)
#pragma unroll
        for (int b = 0; b < 2; b++)
#pragma unroll
            for (int c = 0; c < 4; c++)
#pragma unroll
                for (int d = 0; d < 4; d++) acc[a][b][c][d] = 0.f;

    uint32_t asb[2][2], bhb[2];
#pragma unroll
    for (int s = 0; s < 2; s++) {
        asb[s][0] = (uint32_t)__cvta_generic_to_shared(&As[s][0][0]);
        asb[s][1] = (uint32_t)__cvta_generic_to_shared(&As[s][1][0]);
        bhb[s] = (uint32_t)__cvta_generic_to_shared(&Bh[s][0]);
    }

    auto issue = [&](int stage, int k0) {
        int kk0 = k0 >> 1;
#pragma unroll
        for (int c = tid; c < 512; c += 256) {
            int mat = c >> 8;
            int r = (c >> 1) & 127;
            int q = c & 1;
            const __half* srca = (mat ? Av : Am) + (size_t)(bm_base + r) * HID + k0 + q * 8;
            cp16(asb[stage][mat] + (uint32_t)(r * A2PAD + q * 8) * 2, srca, 16);
        }
        {
            int c = tid;
            int mat = c >> 7;
            int pr = (c >> 4) & 7;
            int q = c & 15;
            const __half2* srcb = g_w2 + ((mat * 64 + kk0 + pr) * 64 + q * 4);
            uint32_t dstb = bhb[stage] + (uint32_t)(pr * BPAD2 + mat * 64 + q * 4) * 4;
            cp16(dstb, srcb, 16);
        }
        cp_commit();
    };

    issue(0, 0);

    const int NITER = HID / 16;   // 8
    for (int it = 0; it < NITER; it++) {
        int stage = it & 1;
        if (it + 1 < NITER) {
            issue(stage ^ 1, (it + 1) * 16);
            cp_wait<1>();
        } else {
            cp_wait<0>();
        }
        __syncthreads();

        const uint32_t* bh = Bh[stage];

#pragma unroll
        for (int mat = 0; mat < 2; mat++) {
            const __half* as = As[stage][mat];
            uint32_t a[2][4];
#pragma unroll
            for (int mt = 0; mt < 2; mt++) {
                int rb = warp_m * 32 + mt * 16;
                const __half* r0 = as + (rb + gid) * A2PAD;
                const __half* r1 = as + (rb + gid + 8) * A2PAD;
                a[mt][0] = *reinterpret_cast<const uint32_t*>(r0 + 2 * tig);
                a[mt][1] = *reinterpret_cast<const uint32_t*>(r1 + 2 * tig);
                a[mt][2] = *reinterpret_cast<const uint32_t*>(r0 + 2 * tig + 8);
                a[mt][3] = *reinterpret_cast<const uint32_t*>(r1 + 2 * tig + 8);
            }
#pragma unroll
            for (int nt = 0; nt < 4; nt++) {
                int col = mat * 64 + warp_n * 32 + nt * 8 + gid;
                uint32_t bh0 = bh[tig * BPAD2 + col];
                uint32_t bh1 = bh[(tig + 4) * BPAD2 + col];
#pragma unroll
                for (int mt = 0; mt < 2; mt++) {
                    mma_f16(acc[mat][mt][nt], a[mt][0], a[mt][1], a[mt][2], a[mt][3], bh0, bh1);
                }
            }
        }
        __syncthreads();
    }

#pragma unroll
    for (int nt = 0; nt < 4; nt++) {
        int gc = warp_n * 32 + nt * 8 + tig * 2;
        float bm0 = bm[gc], bm1 = bm[gc + 1];
        float bv0 = bv[gc], bv1 = bv[gc + 1];
#pragma unroll
        for (int mt = 0; mt < 2; mt++) {
#pragma unroll
            for (int half = 0; half < 2; half++) {
                int gm = bm_base + warp_m * 32 + mt * 16 + gid + half * 8;
                float n1 = g_norm1[gm];
                float n2 = g_norm2[gm];
                float mean0 = fmaxf(acc[0][mt][nt][half * 2 + 0] + bm0, 0.f);
                float mean1 = fmaxf(acc[0][mt][nt][half * 2 + 1] + bm1, 0.f);
                float var0  = fmaxf(acc[1][mt][nt][half * 2 + 0] + bv0, 0.f);
                float var1  = fmaxf(acc[1][mt][nt][half * 2 + 1] + bv1, 0.f);
                float att0 = expf(-var0), att1 = expf(-var1);
                float2 om = make_float2(mean0 * att0 * n1, mean1 * att1 * n1);
                float2 ov = make_float2(var0 * att0 * att0 * n2, var1 * att1 * att1 * n2);
                *reinterpret_cast<__half2*>(Cm + (size_t)gm * OUTF + gc) = __float22half2_rn(om);
                *reinterpret_cast<__half2*>(Cv + (size_t)gm * OUTF + gc) = __float22half2_rn(ov);
            }
        }
    }
}

// ---------------- aggregation: warp per node, CSR pure-read reduce (fp16 in/out) ----------------
__global__ void k_agg1(const __half* __restrict__ msrc, const __half* __restrict__ vsrc,
                       __half* __restrict__ mdst, __half* __restrict__ vdst, int n) {
    int warp = (blockIdx.x * blockDim.x + threadIdx.x) >> 5;
    int lane = threadIdx.x & 31;
    if (warp >= n) return;
    const int D = 128;
    int start = g_offs[warp], end = g_offs[warp + 1];

    float am[4] = {0.f, 0.f, 0.f, 0.f};
    float av[4] = {0.f, 0.f, 0.f, 0.f};
    for (int e = start; e < end; e++) {
        int s = g_csr[e];
        uint2 ar = __ldg(reinterpret_cast<const uint2*>(msrc + (size_t)s * D + lane * 4));
        uint2 br = __ldg(reinterpret_cast<const uint2*>(vsrc + (size_t)s * D + lane * 4));
        float2 a0 = __half22float2(*reinterpret_cast<__half2*>(&ar.x));
        float2 a1 = __half22float2(*reinterpret_cast<__half2*>(&ar.y));
        float2 b0 = __half22float2(*reinterpret_cast<__half2*>(&br.x));
        float2 b1 = __half22float2(*reinterpret_cast<__half2*>(&br.y));
        am[0] += a0.x; am[1] += a0.y; am[2] += a1.x; am[3] += a1.y;
        av[0] += b0.x; av[1] += b0.y; av[2] += b1.x; av[3] += b1.y;
    }
    float n1 = g_norm1[warp], n2 = g_norm2[warp];
#pragma unroll
    for (int j = 0; j < 4; j++) {
        am[j] = fmaxf(am[j] * n1, 0.f);
        av[j] = fmaxf(av[j] * n2, 0.f);
    }
    __half2 m01 = __floats2half2_rn(am[0], am[1]);
    __half2 m23 = __floats2half2_rn(am[2], am[3]);
    __half2 v01 = __floats2half2_rn(av[0], av[1]);
    __half2 v23 = __floats2half2_rn(av[2], av[3]);
    uint2 mo, vo;
    mo.x = *reinterpret_cast<uint32_t*>(&m01); mo.y = *reinterpret_cast<uint32_t*>(&m23);
    vo.x = *reinterpret_cast<uint32_t*>(&v01); vo.y = *reinterpret_cast<uint32_t*>(&v23);
    *reinterpret_cast<uint2*>(mdst + (size_t)warp * D + lane * 4) = mo;
    *reinterpret_cast<uint2*>(vdst + (size_t)warp * D + lane * 4) = vo;
}

// ---------------- threefry-2x32-20 (KAT-verified) ----------------
__device__ __forceinline__ uint32_t rotl32(uint32_t x, int d) {
    return (x << d) | (x >> (32 - d));
}

__device__ __forceinline__ void threefry2x32(uint32_t k0, uint32_t k1,
                                             uint32_t& x0, uint32_t& x1) {
    uint32_t s0 = k0, s1 = k1, s2 = k0 ^ k1 ^ 0x1BD11BDAu;
    x0 += s0; x1 += s1;
#define TFR(r) { x0 += x1; x1 = rotl32(x1, r); x1 ^= x0; }
    TFR(13) TFR(15) TFR(26) TFR(6)   x0 += s1; x1 += s2 + 1u;
    TFR(17) TFR(29) TFR(16) TFR(24)  x0 += s2; x1 += s0 + 2u;
    TFR(13) TFR(15) TFR(26) TFR(6)   x0 += s0; x1 += s1 + 3u;
    TFR(17) TFR(29) TFR(16) TFR(24)  x0 += s1; x1 += s2 + 4u;
    TFR(13) TFR(15) TFR(26) TFR(6)   x0 += s2; x1 += s0 + 5u;
#undef TFR
}

__device__ __forceinline__ float jax_normal_elem(uint32_t idx) {
    uint32_t x0 = 0u, x1 = idx;
    threefry2x32(0u, 42u, x0, x1);
    uint32_t bits = x0 ^ x1;
    uint32_t fb = (bits >> 9) | 0x3F800000u;
    float u01 = __uint_as_float(fb) - 1.0f;
    const float lo = -0.99999994f;
    float u = fmaxf(u01 * 2.0f + lo, lo);
    return 1.41421356f * erfinvf(u);
}

// layer-2 aggregation fused with reparameterization: warp per node, D=64
__global__ void k_agg2_final(const __half* __restrict__ msrc, const __half* __restrict__ vsrc,
                             float* __restrict__ out, int n) {
    int warp = (blockIdx.x * blockDim.x + threadIdx.x) >> 5;
    int lane = threadIdx.x & 31;
    if (warp >= n) return;
    const int D = 64;
    int start = g_offs[warp], end = g_offs[warp + 1];

    float am0 = 0.f, am1 = 0.f, av0 = 0.f, av1 = 0.f;
    for (int e = start; e < end; e++) {
        int s = g_csr[e];
        __half2 ah = __ldg(reinterpret_cast<const __half2*>(msrc + (size_t)s * D + lane * 2));
        __half2 bh = __ldg(reinterpret_cast<const __half2*>(vsrc + (size_t)s * D + lane * 2));
        float2 a = __half22float2(ah);
        float2 b = __half22float2(bh);
        am0 += a.x; am1 += a.y;
        av0 += b.x; av1 += b.y;
    }
    float n1 = g_norm1[warp], n2 = g_norm2[warp];
    float m0 = am0 * n1, m1 = am1 * n1;
    float v0 = av0 * n2, v1 = av1 * n2;

    uint32_t t0 = (uint32_t)(warp * D + lane * 2);
    float e0 = jax_normal_elem(t0);
    float e1 = jax_normal_elem(t0 + 1u);
    float2 o;
    o.x = e0 * sqrtf(v0 + 1e-8f) + m0;
    o.y = e1 * sqrtf(v1 + 1e-8f) + m1;
    *reinterpret_cast<float2*>(out + (size_t)warp * D + lane * 2) = o;
}

// ---------------- launch ----------------
extern "C" void kernel_launch(void* const* d_in, const int* in_sizes, int n_in,
                              void* d_out, int out_size) {
    const float* x       = (const float*)d_in[0];
    const int*   src     = (const int*)d_in[1];
    const int*   dst     = (const int*)d_in[2];
    const float* w_mean1 = (const float*)d_in[3];
    const float* w_var1  = (const float*)d_in[4];
    const float* b_mean1 = (const float*)d_in[5];
    const float* b_var1  = (const float*)d_in[6];
    const float* w_mean2 = (const float*)d_in[7];
    const float* w_var2  = (const float*)d_in[8];
    const float* b_mean2 = (const float*)d_in[9];
    const float* b_var2  = (const float*)d_in[10];
    float* out = (float*)d_out;

    const int N = in_sizes[0] / IN_F;   // 100000
    const int E = in_sizes[1];          // 1600000

    __half* bufA = nullptr; __half* bufB = nullptr;
    __half* aggM = nullptr; __half* aggV = nullptr;
    cudaGetSymbolAddress((void**)&bufA, g_bufA);
    cudaGetSymbolAddress((void**)&bufB, g_bufB);
    cudaGetSymbolAddress((void**)&aggM, g_aggM);
    cudaGetSymbolAddress((void**)&aggV, g_aggV);

    const int T = 256;
    const int NB = (N + 1023) / 1024;

    k_init<<<(N + T - 1) / T, T>>>(w_mean1, w_var1, w_mean2, w_var2, N);
    k_count<<<(E + T - 1) / T, T>>>(dst, E);
    k_scan<<<NB, 1024>>>(N, NB);

    // ---- FUSED: CSR fill + layer-1 GEMM (BM=32, 3 CTAs/SM) ----
    {
        int gemm_blocks = (N + 31) / 32;   // 3125
        k_l1_fused<<<FILLB + gemm_blocks, 256>>>(
            x, b_mean1, b_var1, bufA, bufB, N, src, dst, E);
    }
    {
        int blocks = (N * 32 + T - 1) / T;
        k_agg1<<<blocks, T>>>(bufA, bufB, aggM, aggV, N);
    }
    {
        int blocks = (N + 127) / 128;   // 782, covers M_PAD exactly
        k_l2_f16<<<blocks, 256>>>(aggM, aggV, b_mean2, b_var2, bufA, bufB);
    }
    {
        int blocks = (N * 32 + T - 1) / T;
        k_agg2_final<<<blocks, T>>>(bufA, bufB, out, N);
    }
}

// round 16
// speedup vs baseline: 1.0514x; 1.0514x over previous
#include <cuda_runtime.h>
#include <cuda_fp16.h>
#include <stdint.h>
#include <math.h>

#define NODES_MAX 100000
#define M_PAD     100096
#define EDGES_MAX 1600000
#define IN_F 256
#define HID 128
#define OUTF 64
#define FILLB 512
#define CNTB 1536

// ---------------- scratch (static __device__, no allocs) ----------------
__device__ __half  g_x16[(size_t)M_PAD * IN_F];   // fp16 copy of X
__device__ __half  g_bufA[(size_t)M_PAD * HID];
__device__ __half  g_bufB[(size_t)M_PAD * HID];
__device__ __half  g_aggM[(size_t)M_PAD * HID];
__device__ __half  g_aggV[(size_t)M_PAD * HID];
__device__ float   g_norm1[M_PAD];
__device__ float   g_norm2[M_PAD];
__device__ int     g_deg[NODES_MAX];
__device__ int     g_cursor[NODES_MAX];
__device__ int     g_offs[NODES_MAX + 1];
__device__ int     g_csr[EDGES_MAX];
__device__ int     g_bsum[128];
__device__ int     g_flag[128];
__device__ __half2 g_w1[2 * 128 * 128];   // [mat][K/2][N] k-pair packed
__device__ __half2 g_w2[2 * 64 * 64];

// ---------------- init: zero counters/flags + weight fp16 pack ----------------
__global__ void k_init(const float* __restrict__ Wm1, const float* __restrict__ Wv1,
                       const float* __restrict__ Wm2, const float* __restrict__ Wv2, int n) {
    int i = blockIdx.x * blockDim.x + threadIdx.x;
    if (i < n) { g_deg[i] = 0; g_cursor[i] = 0; }
    if (i < 128) g_flag[i] = 0;
    if (i < 2 * 128 * 128) {
        int mat = i >> 14;
        int rem = i & 16383;
        int kk = rem >> 7;
        int nn = rem & 127;
        const float* W = mat ? Wv1 : Wm1;
        g_w1[i] = __floats2half2_rn(W[(2 * kk) * HID + nn], W[(2 * kk + 1) * HID + nn]);
    }
    if (i < 2 * 64 * 64) {
        int mat = i >> 12;
        int rem = i & 4095;
        int kk = rem >> 6;
        int nn = rem & 63;
        const float* W = mat ? Wv2 : Wm2;
        g_w2[i] = __floats2half2_rn(W[(2 * kk) * OUTF + nn], W[(2 * kk + 1) * OUTF + nn]);
    }
}

// ---------------- fused: degree count + X -> fp16 conversion ----------------
__global__ void k_count_cvt(const int* __restrict__ dst, int E,
                            const float* __restrict__ X, int M) {
    if (blockIdx.x < CNTB) {
        const int stride = CNTB * 256;
        for (int e = blockIdx.x * 256 + threadIdx.x; e < E; e += stride)
            atomicAdd(&g_deg[dst[e]], 1);
        return;
    }
    const int nch = M_PAD * (IN_F / 8);   // 8 floats per chunk
    const int stride = (4096 - CNTB) * 256;
    for (int c = (blockIdx.x - CNTB) * 256 + threadIdx.x; c < nch; c += stride) {
        int row = c >> 5;
        int q = c & 31;
        const float4* s = reinterpret_cast<const float4*>(
            X + (size_t)min(row, M - 1) * IN_F + q * 8);
        float4 a = s[0], b = s[1];
        __half2 h0 = __floats2half2_rn(a.x, a.y);
        __half2 h1 = __floats2half2_rn(a.z, a.w);
        __half2 h2 = __floats2half2_rn(b.x, b.y);
        __half2 h3 = __floats2half2_rn(b.z, b.w);
        uint4 o;
        o.x = *reinterpret_cast<uint32_t*>(&h0);
        o.y = *reinterpret_cast<uint32_t*>(&h1);
        o.z = *reinterpret_cast<uint32_t*>(&h2);
        o.w = *reinterpret_cast<uint32_t*>(&h3);
        *reinterpret_cast<uint4*>(g_x16 + (size_t)row * IN_F + q * 8) = o;
    }
}

// ---------------- single-pass scan (+ fused norms), chained lookback ----------------
__global__ void k_scan(int n, int nb) {
    __shared__ int sm[1024];
    __shared__ int soff;
    int t = threadIdx.x;
    int bid = blockIdx.x;
    int i = bid * 1024 + t;
    int v = (i < n) ? g_deg[i] : 0;
    if (i < n) {
        float d = fmaxf((float)v, 1.0f);
        float n1 = 1.0f / sqrtf(d);
        g_norm1[i] = n1;
        g_norm2[i] = n1 * n1;
    }
    sm[t] = v;
    __syncthreads();
#pragma unroll
    for (int d = 1; d < 1024; d <<= 1) {
        int u = (t >= d) ? sm[t - d] : 0;
        __syncthreads();
        sm[t] += u;
        __syncthreads();
    }
    if (t == 1023) {
        g_bsum[bid] = sm[1023];
        __threadfence();
        atomicExch(&g_flag[bid], 1);
    }
    int acc = 0;
    for (int b = t; b < bid; b += 1024) {
        while (atomicAdd(&g_flag[b], 0) == 0) {}
        acc += g_bsum[b];
    }
#pragma unroll
    for (int o = 16; o; o >>= 1) acc += __shfl_down_sync(0xFFFFFFFFu, acc, o);
    __shared__ int sw[32];
    if ((t & 31) == 0) sw[t >> 5] = acc;
    __syncthreads();
    if (t < 32) {
        int vv = sw[t];
#pragma unroll
        for (int o = 16; o; o >>= 1) vv += __shfl_down_sync(0xFFFFFFFFu, vv, o);
        if (t == 0) soff = vv;
    }
    __syncthreads();
    int off = soff;
    if (i < n) g_offs[i] = off + sm[t] - v;
    if (bid == nb - 1 && t == 1023) g_offs[n] = off + sm[1023];
}

// ================= tensor-core helpers =================
__device__ __forceinline__ void mma_f16(float* d, uint32_t a0, uint32_t a1,
                                        uint32_t a2, uint32_t a3,
                                        uint32_t b0, uint32_t b1) {
    asm volatile(
        "mma.sync.aligned.m16n8k16.row.col.f32.f16.f16.f32 "
        "{%0,%1,%2,%3},{%4,%5,%6,%7},{%8,%9},{%0,%1,%2,%3};"
        : "+f"(d[0]), "+f"(d[1]), "+f"(d[2]), "+f"(d[3])
        : "r"(a0), "r"(a1), "r"(a2), "r"(a3), "r"(b0), "r"(b1));
}

__device__ __forceinline__ void ldsm4(uint32_t& r0, uint32_t& r1, uint32_t& r2, uint32_t& r3,
                                      uint32_t addr) {
    asm volatile("ldmatrix.sync.aligned.m8n8.x4.shared.b16 {%0,%1,%2,%3}, [%4];"
                 : "=r"(r0), "=r"(r1), "=r"(r2), "=r"(r3) : "r"(addr));
}

__device__ __forceinline__ void cp16(uint32_t dst, const void* src, int sz) {
    asm volatile("cp.async.cg.shared.global [%0], [%1], 16, %2;"
                 :: "r"(dst), "l"(src), "r"(sz));
}
__device__ __forceinline__ void cp_commit() {
    asm volatile("cp.async.commit_group;");
}
template <int N> __device__ __forceinline__ void cp_wait() {
    asm volatile("cp.async.wait_group %0;" :: "n"(N));
}

#define A16PAD 40    // halfs per A fp16 smem row (32 + 8); 80B stride, 16B-aligned
#define BPAD2 136    // uint32 words per B pair-row (128 + 8)   [L2]
#define BPAD2N 264   // uint32 words per B pair-row (256 + 8)   [L1]
#define A2PAD 24     // halfs per A smem row (16 + 8)   [L2 fp16 A]

// ================= FUSED: CSR fill + layer-1 GEMM (fp16 A, ldmatrix, k32 stages) =========
// GEMM: BM=64 x 256 out-cols (2 mats x 128), 8 warps: warp_m(2) x 32 rows, warp_n(4) x 32 cols.
__global__ void __launch_bounds__(256)
k_l1_fused(const float* __restrict__ bm, const float* __restrict__ bv,
           __half* __restrict__ Cm, __half* __restrict__ Cv, int M,
           const int* __restrict__ src, const int* __restrict__ dst, int E) {
    // ---- fill blocks ----
    if (blockIdx.x < FILLB) {
        const int stride = FILLB * 256;
        for (int e = blockIdx.x * 256 + threadIdx.x; e < E; e += stride) {
            int d = dst[e];
            int p = atomicAdd(&g_cursor[d], 1);
            g_csr[g_offs[d] + p] = src[e];
        }
        return;
    }

    // ---- GEMM blocks ----
    __shared__ __half   As[2][64 * A16PAD];      // 10240 B
    __shared__ uint32_t Bh[2][16 * BPAD2N];      // 33792 B

    const int tid = threadIdx.x;
    const int lane = tid & 31;
    const int wid = tid >> 5;
    const int warp_m = wid & 1;       // 2 bands of 32 rows
    const int warp_n = wid >> 1;      // 4 bands of 32 cols
    const int gid = lane >> 2;
    const int tig = lane & 3;
    const int bm_base = (blockIdx.x - FILLB) * 64;

    // ldmatrix per-lane source mapping (A fragment order a0,a1,a2,a3)
    const int a_row = (lane & 7) + ((lane >> 3) & 1) * 8;   // 0..15
    const int a_k   = (lane >> 4) * 8;                       // 0 or 8 halfs

    float acc[2][2][4][4];   // [matrix][mt][nt][reg]
#pragma unroll
    for (int a = 0; a < 2; a++)
#pragma unroll
        for (int b = 0; b < 2; b++)
#pragma unroll
            for (int c = 0; c < 4; c++)
#pragma unroll
                for (int d = 0; d < 4; d++) acc[a][b][c][d] = 0.f;

    uint32_t asb[2], bhb[2];
#pragma unroll
    for (int s = 0; s < 2; s++) {
        asb[s] = (uint32_t)__cvta_generic_to_shared(&As[s][0]);
        bhb[s] = (uint32_t)__cvta_generic_to_shared(&Bh[s][0]);
    }

    auto issue = [&](int stage, int k0) {
        int kk0 = k0 >> 1;
        // A tile: 64 rows x 32 halfs = 256 x 16B (1 chunk/thread); rows < M_PAD always
        {
            int r = tid >> 2, q = tid & 3;
            const __half* srca = g_x16 + (size_t)(bm_base + r) * IN_F + k0 + q * 8;
            cp16(asb[stage] + (uint32_t)(r * A16PAD + q * 8) * 2, srca, 16);
        }
        // B tile: 16 kpair-rows x 2 mats x 32 chunks = 1024 x 16B (4/thread)
#pragma unroll
        for (int c = tid; c < 1024; c += 256) {
            int mat = c >> 9;
            int pr = (c >> 5) & 15;
            int q = c & 31;
            const __half2* srcb = g_w1 + ((mat * 128 + kk0 + pr) * 128 + q * 4);
            uint32_t dstb = bhb[stage] + (uint32_t)(pr * BPAD2N + mat * 128 + q * 4) * 4;
            cp16(dstb, srcb, 16);
        }
        cp_commit();
    };

    issue(0, 0);

    const int NST = IN_F / 32;   // 8 stages of k32
    for (int st = 0; st < NST; st++) {
        int stage = st & 1;
        if (st + 1 < NST) {
            issue(stage ^ 1, (st + 1) * 32);
            cp_wait<1>();
        } else {
            cp_wait<0>();
        }
        __syncthreads();

        const uint32_t* bh = Bh[stage];

#pragma unroll
        for (int ks = 0; ks < 2; ks++) {
            // A fragments via ldmatrix (2 m-tiles)
            uint32_t af[2][4];
#pragma unroll
            for (int mt = 0; mt < 2; mt++) {
                uint32_t addr = asb[stage] +
                    (uint32_t)((warp_m * 32 + mt * 16 + a_row) * A16PAD + ks * 16 + a_k) * 2;
                ldsm4(af[mt][0], af[mt][1], af[mt][2], af[mt][3], addr);
            }
            const int kpr = ks * 8;
#pragma unroll
            for (int mat = 0; mat < 2; mat++) {
#pragma unroll
                for (int nt = 0; nt < 4; nt++) {
                    int col = mat * 128 + warp_n * 32 + nt * 8 + gid;
                    uint32_t bh0 = bh[(kpr + tig) * BPAD2N + col];
                    uint32_t bh1 = bh[(kpr + tig + 4) * BPAD2N + col];
#pragma unroll
                    for (int mt = 0; mt < 2; mt++) {
                        mma_f16(acc[mat][mt][nt], af[mt][0], af[mt][1], af[mt][2], af[mt][3],
                                bh0, bh1);
                    }
                }
            }
        }
        __syncthreads();
    }

    // ---- epilogue: bias + relu + att + norms -> fp16 messages ----
#pragma unroll
    for (int nt = 0; nt < 4; nt++) {
        int gc = warp_n * 32 + nt * 8 + tig * 2;
        float bm0 = bm[gc], bm1 = bm[gc + 1];
        float bv0 = bv[gc], bv1 = bv[gc + 1];
#pragma unroll
        for (int mt = 0; mt < 2; mt++) {
#pragma unroll
            for (int half = 0; half < 2; half++) {
                int gm = bm_base + warp_m * 32 + mt * 16 + gid + half * 8;
                float n1 = g_norm1[gm];
                float n2 = g_norm2[gm];
                float mean0 = fmaxf(acc[0][mt][nt][half * 2 + 0] + bm0, 0.f);
                float mean1 = fmaxf(acc[0][mt][nt][half * 2 + 1] + bm1, 0.f);
                float var0  = fmaxf(acc[1][mt][nt][half * 2 + 0] + bv0, 0.f);
                float var1  = fmaxf(acc[1][mt][nt][half * 2 + 1] + bv1, 0.f);
                float att0 = expf(-var0), att1 = expf(-var1);
                float2 om = make_float2(mean0 * att0 * n1, mean1 * att1 * n1);
                float2 ov = make_float2(var0 * att0 * att0 * n2, var1 * att1 * att1 * n2);
                *reinterpret_cast<__half2*>(Cm + (size_t)gm * HID + gc) = __float22half2_rn(om);
                *reinterpret_cast<__half2*>(Cv + (size_t)gm * HID + gc) = __float22half2_rn(ov);
            }
        }
    }
}

// ================= layer-2: dual-A (fp16) GEMM, 1-term, fp16 weights =================
__global__ void __launch_bounds__(256)
k_l2_f16(const __half* __restrict__ Am, const __half* __restrict__ Av,
         const float* __restrict__ bm, const float* __restrict__ bv,
         __half* __restrict__ Cm, __half* __restrict__ Cv) {
    __shared__ __half   As[2][2][128 * A2PAD];
    __shared__ uint32_t Bh[2][8 * BPAD2];

    const int tid = threadIdx.x;
    const int lane = tid & 31;
    const int wid = tid >> 5;
    const int warp_m = wid & 3;
    const int warp_n = wid >> 2;
    const int gid = lane >> 2;
    const int tig = lane & 3;
    const int bm_base = blockIdx.x * 128;

    float acc[2][2][4][4];
#pragma unroll
    for (int a = 0; a < 2; a++)
#pragma unroll
        for (int b = 0; b < 2; b++)
#pragma unroll
            for (int c = 0; c < 4; c++)
#pragma unroll
                for (int d = 0; d < 4; d++) acc[a][b][c][d] = 0.f;

    uint32_t asb[2][2], bhb[2];
#pragma unroll
    for (int s = 0; s < 2; s++) {
        asb[s][0] = (uint32_t)__cvta_generic_to_shared(&As[s][0][0]);
        asb[s][1] = (uint32_t)__cvta_generic_to_shared(&As[s][1][0]);
        bhb[s] = (uint32_t)__cvta_generic_to_shared(&Bh[s][0]);
    }

    auto issue = [&](int stage, int k0) {
        int kk0 = k0 >> 1;
#pragma unroll
        for (int c = tid; c < 512; c += 256) {
            int mat = c >> 8;
            int r = (c >> 1) & 127;
            int q = c & 1;
            const __half* srca = (mat ? Av : Am) + (size_t)(bm_base + r) * HID + k0 + q * 8;
            cp16(asb[stage][mat] + (uint32_t)(r * A2PAD + q * 8) * 2, srca, 16);
        }
        {
            int c = tid;
            int mat = c >> 7;
            int pr = (c >> 4) & 7;
            int q = c & 15;
            const __half2* srcb = g_w2 + ((mat * 64 + kk0 + pr) * 64 + q * 4);
            uint32_t dstb = bhb[stage] + (uint32_t)(pr * BPAD2 + mat * 64 + q * 4) * 4;
            cp16(dstb, srcb, 16);
        }
        cp_commit();
    };

    issue(0, 0);

    const int NITER = HID / 16;   // 8
    for (int it = 0; it < NITER; it++) {
        int stage = it & 1;
        if (it + 1 < NITER) {
            issue(stage ^ 1, (it + 1) * 16);
            cp_wait<1>();
        } else {
            cp_wait<0>();
        }
        __syncthreads();

        const uint32_t* bh = Bh[stage];

#pragma unroll
        for (int mat = 0; mat < 2; mat++) {
            const __half* as = As[stage][mat];
            uint32_t a[2][4];
#pragma unroll
            for (int mt = 0; mt < 2; mt++) {
                int rb = warp_m * 32 + mt * 16;
                const __half* r0 = as + (rb + gid) * A2PAD;
                const __half* r1 = as + (rb + gid + 8) * A2PAD;
                a[mt][0] = *reinterpret_cast<const uint32_t*>(r0 + 2 * tig);
                a[mt][1] = *reinterpret_cast<const uint32_t*>(r1 + 2 * tig);
                a[mt][2] = *reinterpret_cast<const uint32_t*>(r0 + 2 * tig + 8);
                a[mt][3] = *reinterpret_cast<const uint32_t*>(r1 + 2 * tig + 8);
            }
#pragma unroll
            for (int nt = 0; nt < 4; nt++) {
                int col = mat * 64 + warp_n * 32 + nt * 8 + gid;
                uint32_t bh0 = bh[tig * BPAD2 + col];
                uint32_t bh1 = bh[(tig + 4) * BPAD2 + col];
#pragma unroll
                for (int mt = 0; mt < 2; mt++) {
                    mma_f16(acc[mat][mt][nt], a[mt][0], a[mt][1], a[mt][2], a[mt][3], bh0, bh1);
                }
            }
        }
        __syncthreads();
    }

#pragma unroll
    for (int nt = 0; nt < 4; nt++) {
        int gc = warp_n * 32 + nt * 8 + tig * 2;
        float bm0 = bm[gc], bm1 = bm[gc + 1];
        float bv0 = bv[gc], bv1 = bv[gc + 1];
#pragma unroll
        for (int mt = 0; mt < 2; mt++) {
#pragma unroll
            for (int half = 0; half < 2; half++) {
                int gm = bm_base + warp_m * 32 + mt * 16 + gid + half * 8;
                float n1 = g_norm1[gm];
                float n2 = g_norm2[gm];
                float mean0 = fmaxf(acc[0][mt][nt][half * 2 + 0] + bm0, 0.f);
                float mean1 = fmaxf(acc[0][mt][nt][half * 2 + 1] + bm1, 0.f);
                float var0  = fmaxf(acc[1][mt][nt][half * 2 + 0] + bv0, 0.f);
                float var1  = fmaxf(acc[1][mt][nt][half * 2 + 1] + bv1, 0.f);
                float att0 = expf(-var0), att1 = expf(-var1);
                float2 om = make_float2(mean0 * att0 * n1, mean1 * att1 * n1);
                float2 ov = make_float2(var0 * att0 * att0 * n2, var1 * att1 * att1 * n2);
                *reinterpret_cast<__half2*>(Cm + (size_t)gm * OUTF + gc) = __float22half2_rn(om);
                *reinterpret_cast<__half2*>(Cv + (size_t)gm * OUTF + gc) = __float22half2_rn(ov);
            }
        }
    }
}

// ---------------- aggregation: warp per node, CSR pure-read reduce (fp16 in/out) ----------------
__global__ void k_agg1(const __half* __restrict__ msrc, const __half* __restrict__ vsrc,
                       __half* __restrict__ mdst, __half* __restrict__ vdst, int n) {
    int warp = (blockIdx.x * blockDim.x + threadIdx.x) >> 5;
    int lane = threadIdx.x & 31;
    if (warp >= n) return;
    const int D = 128;
    int start = g_offs[warp], end = g_offs[warp + 1];

    float am[4] = {0.f, 0.f, 0.f, 0.f};
    float av[4] = {0.f, 0.f, 0.f, 0.f};
    for (int e = start; e < end; e++) {
        int s = g_csr[e];
        uint2 ar = __ldg(reinterpret_cast<const uint2*>(msrc + (size_t)s * D + lane * 4));
        uint2 br = __ldg(reinterpret_cast<const uint2*>(vsrc + (size_t)s * D + lane * 4));
        float2 a0 = __half22float2(*reinterpret_cast<__half2*>(&ar.x));
        float2 a1 = __half22float2(*reinterpret_cast<__half2*>(&ar.y));
        float2 b0 = __half22float2(*reinterpret_cast<__half2*>(&br.x));
        float2 b1 = __half22float2(*reinterpret_cast<__half2*>(&br.y));
        am[0] += a0.x; am[1] += a0.y; am[2] += a1.x; am[3] += a1.y;
        av[0] += b0.x; av[1] += b0.y; av[2] += b1.x; av[3] += b1.y;
    }
    float n1 = g_norm1[warp], n2 = g_norm2[warp];
#pragma unroll
    for (int j = 0; j < 4; j++) {
        am[j] = fmaxf(am[j] * n1, 0.f);
        av[j] = fmaxf(av[j] * n2, 0.f);
    }
    __half2 m01 = __floats2half2_rn(am[0], am[1]);
    __half2 m23 = __floats2half2_rn(am[2], am[3]);
    __half2 v01 = __floats2half2_rn(av[0], av[1]);
    __half2 v23 = __floats2half2_rn(av[2], av[3]);
    uint2 mo, vo;
    mo.x = *reinterpret_cast<uint32_t*>(&m01); mo.y = *reinterpret_cast<uint32_t*>(&m23);
    vo.x = *reinterpret_cast<uint32_t*>(&v01); vo.y = *reinterpret_cast<uint32_t*>(&v23);
    *reinterpret_cast<uint2*>(mdst + (size_t)warp * D + lane * 4) = mo;
    *reinterpret_cast<uint2*>(vdst + (size_t)warp * D + lane * 4) = vo;
}

// ---------------- threefry-2x32-20 (KAT-verified) ----------------
__device__ __forceinline__ uint32_t rotl32(uint32_t x, int d) {
    return (x << d) | (x >> (32 - d));
}

__device__ __forceinline__ void threefry2x32(uint32_t k0, uint32_t k1,
                                             uint32_t& x0, uint32_t& x1) {
    uint32_t s0 = k0, s1 = k1, s2 = k0 ^ k1 ^ 0x1BD11BDAu;
    x0 += s0; x1 += s1;
#define TFR(r) { x0 += x1; x1 = rotl32(x1, r); x1 ^= x0; }
    TFR(13) TFR(15) TFR(26) TFR(6)   x0 += s1; x1 += s2 + 1u;
    TFR(17) TFR(29) TFR(16) TFR(24)  x0 += s2; x1 += s0 + 2u;
    TFR(13) TFR(15) TFR(26) TFR(6)   x0 += s0; x1 += s1 + 3u;
    TFR(17) TFR(29) TFR(16) TFR(24)  x0 += s1; x1 += s2 + 4u;
    TFR(13) TFR(15) TFR(26) TFR(6)   x0 += s2; x1 += s0 + 5u;
#undef TFR
}

__device__ __forceinline__ float jax_normal_elem(uint32_t idx) {
    uint32_t x0 = 0u, x1 = idx;
    threefry2x32(0u, 42u, x0, x1);
    uint32_t bits = x0 ^ x1;
    uint32_t fb = (bits >> 9) | 0x3F800000u;
    float u01 = __uint_as_float(fb) - 1.0f;
    const float lo = -0.99999994f;
    float u = fmaxf(u01 * 2.0f + lo, lo);
    return 1.41421356f * erfinvf(u);
}

// layer-2 aggregation fused with reparameterization: warp per node, D=64
__global__ void k_agg2_final(const __half* __restrict__ msrc, const __half* __restrict__ vsrc,
                             float* __restrict__ out, int n) {
    int warp = (blockIdx.x * blockDim.x + threadIdx.x) >> 5;
    int lane = threadIdx.x & 31;
    if (warp >= n) return;
    const int D = 64;
    int start = g_offs[warp], end = g_offs[warp + 1];

    float am0 = 0.f, am1 = 0.f, av0 = 0.f, av1 = 0.f;
    for (int e = start; e < end; e++) {
        int s = g_csr[e];
        __half2 ah = __ldg(reinterpret_cast<const __half2*>(msrc + (size_t)s * D + lane * 2));
        __half2 bh = __ldg(reinterpret_cast<const __half2*>(vsrc + (size_t)s * D + lane * 2));
        float2 a = __half22float2(ah);
        float2 b = __half22float2(bh);
        am0 += a.x; am1 += a.y;
        av0 += b.x; av1 += b.y;
    }
    float n1 = g_norm1[warp], n2 = g_norm2[warp];
    float m0 = am0 * n1, m1 = am1 * n1;
    float v0 = av0 * n2, v1 = av1 * n2;

    uint32_t t0 = (uint32_t)(warp * D + lane * 2);
    float e0 = jax_normal_elem(t0);
    float e1 = jax_normal_elem(t0 + 1u);
    float2 o;
    o.x = e0 * sqrtf(v0 + 1e-8f) + m0;
    o.y = e1 * sqrtf(v1 + 1e-8f) + m1;
    *reinterpret_cast<float2*>(out + (size_t)warp * D + lane * 2) = o;
}

// ---------------- launch ----------------
extern "C" void kernel_launch(void* const* d_in, const int* in_sizes, int n_in,
                              void* d_out, int out_size) {
    const float* x       = (const float*)d_in[0];
    const int*   src     = (const int*)d_in[1];
    const int*   dst     = (const int*)d_in[2];
    const float* w_mean1 = (const float*)d_in[3];
    const float* w_var1  = (const float*)d_in[4];
    const float* b_mean1 = (const float*)d_in[5];
    const float* b_var1  = (const float*)d_in[6];
    const float* w_mean2 = (const float*)d_in[7];
    const float* w_var2  = (const float*)d_in[8];
    const float* b_mean2 = (const float*)d_in[9];
    const float* b_var2  = (const float*)d_in[10];
    float* out = (float*)d_out;

    const int N = in_sizes[0] / IN_F;   // 100000
    const int E = in_sizes[1];          // 1600000

    __half* bufA = nullptr; __half* bufB = nullptr;
    __half* aggM = nullptr; __half* aggV = nullptr;
    cudaGetSymbolAddress((void**)&bufA, g_bufA);
    cudaGetSymbolAddress((void**)&bufB, g_bufB);
    cudaGetSymbolAddress((void**)&aggM, g_aggM);
    cudaGetSymbolAddress((void**)&aggV, g_aggV);

    const int T = 256;
    const int NB = (N + 1023) / 1024;

    k_init<<<(N + T - 1) / T, T>>>(w_mean1, w_var1, w_mean2, w_var2, N);
    k_count_cvt<<<4096, T>>>(dst, E, x, N);
    k_scan<<<NB, 1024>>>(N, NB);

    // ---- FUSED: CSR fill + layer-1 GEMM (fp16 A, ldmatrix, k32 stages) ----
    {
        int gemm_blocks = (N + 63) / 64;   // 1563
        k_l1_fused<<<FILLB + gemm_blocks, 256>>>(
            b_mean1, b_var1, bufA, bufB, N, src, dst, E);
    }
    {
        int blocks = (N * 32 + T - 1) / T;
        k_agg1<<<blocks, T>>>(bufA, bufB, aggM, aggV, N);
    }
    {
        int blocks = (N + 127) / 128;   // 782, covers M_PAD exactly
        k_l2_f16<<<blocks, 256>>>(aggM, aggV, b_mean2, b_var2, bufA, bufB);
    }
    {
        int blocks = (N * 32 + T - 1) / T;
        k_agg2_final<<<blocks, T>>>(bufA, bufB, out, N);
    }
}

// round 17
// speedup vs baseline: 1.1158x; 1.0613x over previous
#include <cuda_runtime.h>
#include <cuda_fp16.h>
#include <stdint.h>
#include <math.h>

#define NODES_MAX 100000
#define M_PAD     100096
#define EDGES_MAX 1600000
#define IN_F 256
#define HID 128
#define OUTF 64
#define FILLB 512

// ---------------- scratch (static __device__, no allocs) ----------------
__device__ __half  g_bufA[(size_t)M_PAD * HID];
__device__ __half  g_bufB[(size_t)M_PAD * HID];
__device__ __half  g_aggM[(size_t)M_PAD * HID];
__device__ __half  g_aggV[(size_t)M_PAD * HID];
__device__ float   g_norm1[M_PAD];
__device__ float   g_norm2[M_PAD];
__device__ int     g_deg[NODES_MAX];
__device__ int     g_cursor[NODES_MAX];
__device__ int     g_offs[NODES_MAX + 1];
__device__ int     g_csr[EDGES_MAX];
__device__ int     g_bsum[128];
__device__ int     g_flag[128];
__device__ __half2 g_w1[2 * 128 * 128];   // [mat][K/2][N] k-pair packed
__device__ __half2 g_w2[2 * 64 * 64];

// ---------------- init: zero counters/flags + weight fp16 pack ----------------
__global__ void k_init(const float* __restrict__ Wm1, const float* __restrict__ Wv1,
                       const float* __restrict__ Wm2, const float* __restrict__ Wv2, int n) {
    int i = blockIdx.x * blockDim.x + threadIdx.x;
    if (i < n) { g_deg[i] = 0; g_cursor[i] = 0; }
    if (i < 128) g_flag[i] = 0;
    if (i < 2 * 128 * 128) {
        int mat = i >> 14;
        int rem = i & 16383;
        int kk = rem >> 7;
        int nn = rem & 127;
        const float* W = mat ? Wv1 : Wm1;
        g_w1[i] = __floats2half2_rn(W[(2 * kk) * HID + nn], W[(2 * kk + 1) * HID + nn]);
    }
    if (i < 2 * 64 * 64) {
        int mat = i >> 12;
        int rem = i & 4095;
        int kk = rem >> 6;
        int nn = rem & 63;
        const float* W = mat ? Wv2 : Wm2;
        g_w2[i] = __floats2half2_rn(W[(2 * kk) * OUTF + nn], W[(2 * kk + 1) * OUTF + nn]);
    }
}

__global__ void k_count(const int* __restrict__ dst, int E) {
    int e = blockIdx.x * blockDim.x + threadIdx.x;
    if (e < E) atomicAdd(&g_deg[dst[e]], 1);
}

// ---------------- single-pass scan (+ fused norms), chained lookback ----------------
__global__ void k_scan(int n, int nb) {
    __shared__ int sm[1024];
    __shared__ int soff;
    int t = threadIdx.x;
    int bid = blockIdx.x;
    int i = bid * 1024 + t;
    int v = (i < n) ? g_deg[i] : 0;
    if (i < n) {
        float d = fmaxf((float)v, 1.0f);
        float n1 = 1.0f / sqrtf(d);
        g_norm1[i] = n1;
        g_norm2[i] = n1 * n1;
    }
    sm[t] = v;
    __syncthreads();
#pragma unroll
    for (int d = 1; d < 1024; d <<= 1) {
        int u = (t >= d) ? sm[t - d] : 0;
        __syncthreads();
        sm[t] += u;
        __syncthreads();
    }
    if (t == 1023) {
        g_bsum[bid] = sm[1023];
        __threadfence();
        atomicExch(&g_flag[bid], 1);
    }
    int acc = 0;
    for (int b = t; b < bid; b += 1024) {
        while (atomicAdd(&g_flag[b], 0) == 0) {}
        acc += g_bsum[b];
    }
#pragma unroll
    for (int o = 16; o; o >>= 1) acc += __shfl_down_sync(0xFFFFFFFFu, acc, o);
    __shared__ int sw[32];
    if ((t & 31) == 0) sw[t >> 5] = acc;
    __syncthreads();
    if (t < 32) {
        int vv = sw[t];
#pragma unroll
        for (int o = 16; o; o >>= 1) vv += __shfl_down_sync(0xFFFFFFFFu, vv, o);
        if (t == 0) soff = vv;
    }
    __syncthreads();
    int off = soff;
    if (i < n) g_offs[i] = off + sm[t] - v;
    if (bid == nb - 1 && t == 1023) g_offs[n] = off + sm[1023];
}

// ================= tensor-core helpers =================
__device__ __forceinline__ void mma_f16(float* d, uint32_t a0, uint32_t a1,
                                        uint32_t a2, uint32_t a3,
                                        uint32_t b0, uint32_t b1) {
    asm volatile(
        "mma.sync.aligned.m16n8k16.row.col.f32.f16.f16.f32 "
        "{%0,%1,%2,%3},{%4,%5,%6,%7},{%8,%9},{%0,%1,%2,%3};"
        : "+f"(d[0]), "+f"(d[1]), "+f"(d[2]), "+f"(d[3])
        : "r"(a0), "r"(a1), "r"(a2), "r"(a3), "r"(b0), "r"(b1));
}

__device__ __forceinline__ void ldsm4(uint32_t& r0, uint32_t& r1, uint32_t& r2, uint32_t& r3,
                                      uint32_t addr) {
    asm volatile("ldmatrix.sync.aligned.m8n8.x4.shared.b16 {%0,%1,%2,%3}, [%4];"
                 : "=r"(r0), "=r"(r1), "=r"(r2), "=r"(r3) : "r"(addr));
}

__device__ __forceinline__ void cp16(uint32_t dst, const void* src, int sz) {
    asm volatile("cp.async.cg.shared.global [%0], [%1], 16, %2;"
                 :: "r"(dst), "l"(src), "r"(sz));
}
__device__ __forceinline__ void cp_commit() {
    asm volatile("cp.async.commit_group;");
}
template <int N> __device__ __forceinline__ void cp_wait() {
    asm volatile("cp.async.wait_group %0;" :: "n"(N));
}

#define A16PAD 40    // halfs per A fp16 smem row (32 + 8); 80B stride, 16B-aligned
#define BPAD2 136    // uint32 words per B pair-row (128 + 8)   [L2]
#define BPAD2N 264   // uint32 words per B pair-row (256 + 8)   [L1]
#define A2PAD 24     // halfs per A smem row (16 + 8)   [L2 fp16 A]

// ================= FUSED: CSR fill + layer-1 GEMM (in-CTA fp16 cvt, ldmatrix, k32) ======
// GEMM: BM=64 x 256 out-cols (2 mats x 128). A: fp32 LDG (prefetched regs) -> cvt -> fp16 STS.
__global__ void __launch_bounds__(256)
k_l1_fused(const float* __restrict__ X,
           const float* __restrict__ bm, const float* __restrict__ bv,
           __half* __restrict__ Cm, __half* __restrict__ Cv, int M,
           const int* __restrict__ src, const int* __restrict__ dst, int E) {
    // ---- fill blocks ----
    if (blockIdx.x < FILLB) {
        const int stride = FILLB * 256;
        for (int e = blockIdx.x * 256 + threadIdx.x; e < E; e += stride) {
            int d = dst[e];
            int p = atomicAdd(&g_cursor[d], 1);
            g_csr[g_offs[d] + p] = src[e];
        }
        return;
    }

    // ---- GEMM blocks ----
    __shared__ __half   As[2][64 * A16PAD];      // 10240 B
    __shared__ uint32_t Bh[2][16 * BPAD2N];      // 33792 B

    const int tid = threadIdx.x;
    const int lane = tid & 31;
    const int wid = tid >> 5;
    const int warp_m = wid & 1;       // 2 bands of 32 rows
    const int warp_n = wid >> 1;      // 4 bands of 32 cols
    const int gid = lane >> 2;
    const int tig = lane & 3;
    const int bm_base = (blockIdx.x - FILLB) * 64;

    // ldmatrix per-lane source mapping
    const int a_row = (lane & 7) + ((lane >> 3) & 1) * 8;   // 0..15
    const int a_k   = (lane >> 4) * 8;                       // 0 or 8 halfs

    // A load/store mapping: thread -> row(tid>>2), 8 floats at q(tid&3)*8
    const int ar = tid >> 2;
    const int aq = tid & 3;
    const float* aptr = X + (size_t)min(bm_base + ar, M - 1) * IN_F + aq * 8;

    float acc[2][2][4][4];   // [matrix][mt][nt][reg]
#pragma unroll
    for (int a = 0; a < 2; a++)
#pragma unroll
        for (int b = 0; b < 2; b++)
#pragma unroll
            for (int c = 0; c < 4; c++)
#pragma unroll
                for (int d = 0; d < 4; d++) acc[a][b][c][d] = 0.f;

    uint32_t asb[2], bhb[2];
#pragma unroll
    for (int s = 0; s < 2; s++) {
        asb[s] = (uint32_t)__cvta_generic_to_shared(&As[s][0]);
        bhb[s] = (uint32_t)__cvta_generic_to_shared(&Bh[s][0]);
    }

    auto issueB = [&](int stage, int k0) {
        int kk0 = k0 >> 1;
#pragma unroll
        for (int c = tid; c < 1024; c += 256) {
            int mat = c >> 9;
            int pr = (c >> 5) & 15;
            int q = c & 31;
            const __half2* srcb = g_w1 + ((mat * 128 + kk0 + pr) * 128 + q * 4);
            uint32_t dstb = bhb[stage] + (uint32_t)(pr * BPAD2N + mat * 128 + q * 4) * 4;
            cp16(dstb, srcb, 16);
        }
        cp_commit();
    };

    auto stA = [&](int stage, float4 ra, float4 rb) {
        __half2 h0 = __floats2half2_rn(ra.x, ra.y);
        __half2 h1 = __floats2half2_rn(ra.z, ra.w);
        __half2 h2 = __floats2half2_rn(rb.x, rb.y);
        __half2 h3 = __floats2half2_rn(rb.z, rb.w);
        uint4 o;
        o.x = *reinterpret_cast<uint32_t*>(&h0);
        o.y = *reinterpret_cast<uint32_t*>(&h1);
        o.z = *reinterpret_cast<uint32_t*>(&h2);
        o.w = *reinterpret_cast<uint32_t*>(&h3);
        *reinterpret_cast<uint4*>(&As[stage][ar * A16PAD + aq * 8]) = o;
    };

    // prefetch stage-0 A into registers; issue stage-0 B
    float4 ra = *reinterpret_cast<const float4*>(aptr);
    float4 rb = *reinterpret_cast<const float4*>(aptr + 4);
    issueB(0, 0);

    const int NST = IN_F / 32;   // 8
    for (int st = 0; st < NST; st++) {
        int stage = st & 1;
        stA(stage, ra, rb);                        // cvt + STS current A
        if (st + 1 < NST) {
            const float* p = aptr + (st + 1) * 32;
            ra = *reinterpret_cast<const float4*>(p);
            rb = *reinterpret_cast<const float4*>(p + 4);
            issueB(stage ^ 1, (st + 1) * 32);
            cp_wait<1>();
        } else {
            cp_wait<0>();
        }
        __syncthreads();

        const uint32_t* bh = Bh[stage];

#pragma unroll
        for (int ks = 0; ks < 2; ks++) {
            uint32_t af[2][4];
#pragma unroll
            for (int mt = 0; mt < 2; mt++) {
                uint32_t addr = asb[stage] +
                    (uint32_t)((warp_m * 32 + mt * 16 + a_row) * A16PAD + ks * 16 + a_k) * 2;
                ldsm4(af[mt][0], af[mt][1], af[mt][2], af[mt][3], addr);
            }
            const int kpr = ks * 8;
#pragma unroll
            for (int mat = 0; mat < 2; mat++) {
#pragma unroll
                for (int nt = 0; nt < 4; nt++) {
                    int col = mat * 128 + warp_n * 32 + nt * 8 + gid;
                    uint32_t bh0 = bh[(kpr + tig) * BPAD2N + col];
                    uint32_t bh1 = bh[(kpr + tig + 4) * BPAD2N + col];
#pragma unroll
                    for (int mt = 0; mt < 2; mt++) {
                        mma_f16(acc[mat][mt][nt], af[mt][0], af[mt][1], af[mt][2], af[mt][3],
                                bh0, bh1);
                    }
                }
            }
        }
        __syncthreads();
    }

    // ---- epilogue: bias + relu + att + norms -> fp16 messages ----
#pragma unroll
    for (int nt = 0; nt < 4; nt++) {
        int gc = warp_n * 32 + nt * 8 + tig * 2;
        float bm0 = bm[gc], bm1 = bm[gc + 1];
        float bv0 = bv[gc], bv1 = bv[gc + 1];
#pragma unroll
        for (int mt = 0; mt < 2; mt++) {
#pragma unroll
            for (int half = 0; half < 2; half++) {
                int gm = bm_base + warp_m * 32 + mt * 16 + gid + half * 8;
                float n1 = g_norm1[gm];
                float n2 = g_norm2[gm];
                float mean0 = fmaxf(acc[0][mt][nt][half * 2 + 0] + bm0, 0.f);
                float mean1 = fmaxf(acc[0][mt][nt][half * 2 + 1] + bm1, 0.f);
                float var0  = fmaxf(acc[1][mt][nt][half * 2 + 0] + bv0, 0.f);
                float var1  = fmaxf(acc[1][mt][nt][half * 2 + 1] + bv1, 0.f);
                float att0 = expf(-var0), att1 = expf(-var1);
                float2 om = make_float2(mean0 * att0 * n1, mean1 * att1 * n1);
                float2 ov = make_float2(var0 * att0 * att0 * n2, var1 * att1 * att1 * n2);
                *reinterpret_cast<__half2*>(Cm + (size_t)gm * HID + gc) = __float22half2_rn(om);
                *reinterpret_cast<__half2*>(Cv + (size_t)gm * HID + gc) = __float22half2_rn(ov);
            }
        }
    }
}

// ================= layer-2: dual-A (fp16) GEMM, 1-term, fp16 weights =================
__global__ void __launch_bounds__(256)
k_l2_f16(const __half* __restrict__ Am, const __half* __restrict__ Av,
         const float* __restrict__ bm, const float* __restrict__ bv,
         __half* __restrict__ Cm, __half* __restrict__ Cv) {
    __shared__ __half   As[2][2][128 * A2PAD];
    __shared__ uint32_t Bh[2][8 * BPAD2];

    const int tid = threadIdx.x;
    const int lane = tid & 31;
    const int wid = tid >> 5;
    const int warp_m = wid & 3;
    const int warp_n = wid >> 2;
    const int gid = lane >> 2;
    const int tig = lane & 3;
    const int bm_base = blockIdx.x * 128;

    float acc[2][2][4][4];
#pragma unroll
    for (int a = 0; a < 2; a++)
#pragma unroll
        for (int b = 0; b < 2; b++)
#pragma unroll
            for (int c = 0; c < 4; c++)
#pragma unroll
                for (int d = 0; d < 4; d++) acc[a][b][c][d] = 0.f;

    uint32_t asb[2][2], bhb[2];
#pragma unroll
    for (int s = 0; s < 2; s++) {
        asb[s][0] = (uint32_t)__cvta_generic_to_shared(&As[s][0][0]);
        asb[s][1] = (uint32_t)__cvta_generic_to_shared(&As[s][1][0]);
        bhb[s] = (uint32_t)__cvta_generic_to_shared(&Bh[s][0]);
    }

    auto issue = [&](int stage, int k0) {
        int kk0 = k0 >> 1;
#pragma unroll
        for (int c = tid; c < 512; c += 256) {
            int mat = c >> 8;
            int r = (c >> 1) & 127;
            int q = c & 1;
            const __half* srca = (mat ? Av : Am) + (size_t)(bm_base + r) * HID + k0 + q * 8;
            cp16(asb[stage][mat] + (uint32_t)(r * A2PAD + q * 8) * 2, srca, 16);
        }
        {
            int c = tid;
            int mat = c >> 7;
            int pr = (c >> 4) & 7;
            int q = c & 15;
            const __half2* srcb = g_w2 + ((mat * 64 + kk0 + pr) * 64 + q * 4);
            uint32_t dstb = bhb[stage] + (uint32_t)(pr * BPAD2 + mat * 64 + q * 4) * 4;
            cp16(dstb, srcb, 16);
        }
        cp_commit();
    };

    issue(0, 0);

    const int NITER = HID / 16;   // 8
    for (int it = 0; it < NITER; it++) {
        int stage = it & 1;
        if (it + 1 < NITER) {
            issue(stage ^ 1, (it + 1) * 16);
            cp_wait<1>();
        } else {
            cp_wait<0>();
        }
        __syncthreads();

        const uint32_t* bh = Bh[stage];

#pragma unroll
        for (int mat = 0; mat < 2; mat++) {
            const __half* as = As[stage][mat];
            uint32_t a[2][4];
#pragma unroll
            for (int mt = 0; mt < 2; mt++) {
                int rb = warp_m * 32 + mt * 16;
                const __half* r0 = as + (rb + gid) * A2PAD;
                const __half* r1 = as + (rb + gid + 8) * A2PAD;
                a[mt][0] = *reinterpret_cast<const uint32_t*>(r0 + 2 * tig);
                a[mt][1] = *reinterpret_cast<const uint32_t*>(r1 + 2 * tig);
                a[mt][2] = *reinterpret_cast<const uint32_t*>(r0 + 2 * tig + 8);
                a[mt][3] = *reinterpret_cast<const uint32_t*>(r1 + 2 * tig + 8);
            }
#pragma unroll
            for (int nt = 0; nt < 4; nt++) {
                int col = mat * 64 + warp_n * 32 + nt * 8 + gid;
                uint32_t bh0 = bh[tig * BPAD2 + col];
                uint32_t bh1 = bh[(tig + 4) * BPAD2 + col];
#pragma unroll
                for (int mt = 0; mt < 2; mt++) {
                    mma_f16(acc[mat][mt][nt], a[mt][0], a[mt][1], a[mt][2], a[mt][3], bh0, bh1);
                }
            }
        }
        __syncthreads();
    }

#pragma unroll
    for (int nt = 0; nt < 4; nt++) {
        int gc = warp_n * 32 + nt * 8 + tig * 2;
        float bm0 = bm[gc], bm1 = bm[gc + 1];
        float bv0 = bv[gc], bv1 = bv[gc + 1];
#pragma unroll
        for (int mt = 0; mt < 2; mt++) {
#pragma unroll
            for (int half = 0; half < 2; half++) {
                int gm = bm_base + warp_m * 32 + mt * 16 + gid + half * 8;
                float n1 = g_norm1[gm];
                float n2 = g_norm2[gm];
                float mean0 = fmaxf(acc[0][mt][nt][half * 2 + 0] + bm0, 0.f);
                float mean1 = fmaxf(acc[0][mt][nt][half * 2 + 1] + bm1, 0.f);
                float var0  = fmaxf(acc[1][mt][nt][half * 2 + 0] + bv0, 0.f);
                float var1  = fmaxf(acc[1][mt][nt][half * 2 + 1] + bv1, 0.f);
                float att0 = expf(-var0), att1 = expf(-var1);
                float2 om = make_float2(mean0 * att0 * n1, mean1 * att1 * n1);
                float2 ov = make_float2(var0 * att0 * att0 * n2, var1 * att1 * att1 * n2);
                *reinterpret_cast<__half2*>(Cm + (size_t)gm * OUTF + gc) = __float22half2_rn(om);
                *reinterpret_cast<__half2*>(Cv + (size_t)gm * OUTF + gc) = __float22half2_rn(ov);
            }
        }
    }
}

// ---------------- aggregation: warp per node, CSR pure-read reduce (fp16 in/out) ----------------
__global__ void k_agg1(const __half* __restrict__ msrc, const __half* __restrict__ vsrc,
                       __half* __restrict__ mdst, __half* __restrict__ vdst, int n) {
    int warp = (blockIdx.x * blockDim.x + threadIdx.x) >> 5;
    int lane = threadIdx.x & 31;
    if (warp >= n) return;
    const int D = 128;
    int start = g_offs[warp], end = g_offs[warp + 1];

    float am[4] = {0.f, 0.f, 0.f, 0.f};
    float av[4] = {0.f, 0.f, 0.f, 0.f};
    for (int e = start; e < end; e++) {
        int s = g_csr[e];
        uint2 ar = __ldg(reinterpret_cast<const uint2*>(msrc + (size_t)s * D + lane * 4));
        uint2 br = __ldg(reinterpret_cast<const uint2*>(vsrc + (size_t)s * D + lane * 4));
        float2 a0 = __half22float2(*reinterpret_cast<__half2*>(&ar.x));
        float2 a1 = __half22float2(*reinterpret_cast<__half2*>(&ar.y));
        float2 b0 = __half22float2(*reinterpret_cast<__half2*>(&br.x));
        float2 b1 = __half22float2(*reinterpret_cast<__half2*>(&br.y));
        am[0] += a0.x; am[1] += a0.y; am[2] += a1.x; am[3] += a1.y;
        av[0] += b0.x; av[1] += b0.y; av[2] += b1.x; av[3] += b1.y;
    }
    float n1 = g_norm1[warp], n2 = g_norm2[warp];
#pragma unroll
    for (int j = 0; j < 4; j++) {
        am[j] = fmaxf(am[j] * n1, 0.f);
        av[j] = fmaxf(av[j] * n2, 0.f);
    }
    __half2 m01 = __floats2half2_rn(am[0], am[1]);
    __half2 m23 = __floats2half2_rn(am[2], am[3]);
    __half2 v01 = __floats2half2_rn(av[0], av[1]);
    __half2 v23 = __floats2half2_rn(av[2], av[3]);
    uint2 mo, vo;
    mo.x = *reinterpret_cast<uint32_t*>(&m01); mo.y = *reinterpret_cast<uint32_t*>(&m23);
    vo.x = *reinterpret_cast<uint32_t*>(&v01); vo.y = *reinterpret_cast<uint32_t*>(&v23);
    *reinterpret_cast<uint2*>(mdst + (size_t)warp * D + lane * 4) = mo;
    *reinterpret_cast<uint2*>(vdst + (size_t)warp * D + lane * 4) = vo;
}

// ---------------- threefry-2x32-20 (KAT-verified) ----------------
__device__ __forceinline__ uint32_t rotl32(uint32_t x, int d) {
    return (x << d) | (x >> (32 - d));
}

__device__ __forceinline__ void threefry2x32(uint32_t k0, uint32_t k1,
                                             uint32_t& x0, uint32_t& x1) {
    uint32_t s0 = k0, s1 = k1, s2 = k0 ^ k1 ^ 0x1BD11BDAu;
    x0 += s0; x1 += s1;
#define TFR(r) { x0 += x1; x1 = rotl32(x1, r); x1 ^= x0; }
    TFR(13) TFR(15) TFR(26) TFR(6)   x0 += s1; x1 += s2 + 1u;
    TFR(17) TFR(29) TFR(16) TFR(24)  x0 += s2; x1 += s0 + 2u;
    TFR(13) TFR(15) TFR(26) TFR(6)   x0 += s0; x1 += s1 + 3u;
    TFR(17) TFR(29) TFR(16) TFR(24)  x0 += s1; x1 += s2 + 4u;
    TFR(13) TFR(15) TFR(26) TFR(6)   x0 += s2; x1 += s0 + 5u;
#undef TFR
}

__device__ __forceinline__ float jax_normal_elem(uint32_t idx) {
    uint32_t x0 = 0u, x1 = idx;
    threefry2x32(0u, 42u, x0, x1);
    uint32_t bits = x0 ^ x1;
    uint32_t fb = (bits >> 9) | 0x3F800000u;
    float u01 = __uint_as_float(fb) - 1.0f;
    const float lo = -0.99999994f;
    float u = fmaxf(u01 * 2.0f + lo, lo);
    return 1.41421356f * erfinvf(u);
}

// layer-2 aggregation fused with reparameterization: warp per node, D=64
__global__ void k_agg2_final(const __half* __restrict__ msrc, const __half* __restrict__ vsrc,
                             float* __restrict__ out, int n) {
    int warp = (blockIdx.x * blockDim.x + threadIdx.x) >> 5;
    int lane = threadIdx.x & 31;
    if (warp >= n) return;
    const int D = 64;
    int start = g_offs[warp], end = g_offs[warp + 1];

    float am0 = 0.f, am1 = 0.f, av0 = 0.f, av1 = 0.f;
    for (int e = start; e < end; e++) {
        int s = g_csr[e];
        __half2 ah = __ldg(reinterpret_cast<const __half2*>(msrc + (size_t)s * D + lane * 2));
        __half2 bh = __ldg(reinterpret_cast<const __half2*>(vsrc + (size_t)s * D + lane * 2));
        float2 a = __half22float2(ah);
        float2 b = __half22float2(bh);
        am0 += a.x; am1 += a.y;
        av0 += b.x; av1 += b.y;
    }
    float n1 = g_norm1[warp], n2 = g_norm2[warp];
    float m0 = am0 * n1, m1 = am1 * n1;
    float v0 = av0 * n2, v1 = av1 * n2;

    uint32_t t0 = (uint32_t)(warp * D + lane * 2);
    float e0 = jax_normal_elem(t0);
    float e1 = jax_normal_elem(t0 + 1u);
    float2 o;
    o.x = e0 * sqrtf(v0 + 1e-8f) + m0;
    o.y = e1 * sqrtf(v1 + 1e-8f) + m1;
    *reinterpret_cast<float2*>(out + (size_t)warp * D + lane * 2) = o;
}

// ---------------- launch ----------------
extern "C" void kernel_launch(void* const* d_in, const int* in_sizes, int n_in,
                              void* d_out, int out_size) {
    const float* x       = (const float*)d_in[0];
    const int*   src     = (const int*)d_in[1];
    const int*   dst     = (const int*)d_in[2];
    const float* w_mean1 = (const float*)d_in[3];
    const float* w_var1  = (const float*)d_in[4];
    const float* b_mean1 = (const float*)d_in[5];
    const float* b_var1  = (const float*)d_in[6];
    const float* w_mean2 = (const float*)d_in[7];
    const float* w_var2  = (const float*)d_in[8];
    const float* b_mean2 = (const float*)d_in[9];
    const float* b_var2  = (const float*)d_in[10];
    float* out = (float*)d_out;

    const int N = in_sizes[0] / IN_F;   // 100000
    const int E = in_sizes[1];          // 1600000

    __half* bufA = nullptr; __half* bufB = nullptr;
    __half* aggM = nullptr; __half* aggV = nullptr;
    cudaGetSymbolAddress((void**)&bufA, g_bufA);
    cudaGetSymbolAddress((void**)&bufB, g_bufB);
    cudaGetSymbolAddress((void**)&aggM, g_aggM);
    cudaGetSymbolAddress((void**)&aggV, g_aggV);

    const int T = 256;
    const int NB = (N + 1023) / 1024;

    k_init<<<(N + T - 1) / T, T>>>(w_mean1, w_var1, w_mean2, w_var2, N);
    k_count<<<(E + T - 1) / T, T>>>(dst, E);
    k_scan<<<NB, 1024>>>(N, NB);

    // ---- FUSED: CSR fill + layer-1 GEMM (in-CTA fp16 cvt, ldmatrix, k32) ----
    {
        int gemm_blocks = (N + 63) / 64;   // 1563
        k_l1_fused<<<FILLB + gemm_blocks, 256>>>(
            x, b_mean1, b_var1, bufA, bufB, N, src, dst, E);
    }
    {
        int blocks = (N * 32 + T - 1) / T;
        k_agg1<<<blocks, T>>>(bufA, bufB, aggM, aggV, N);
    }
    {
        int blocks = (N + 127) / 128;   // 782, covers M_PAD exactly
        k_l2_f16<<<blocks, 256>>>(aggM, aggV, b_mean2, b_var2, bufA, bufB);
    }
    {
        int blocks = (N * 32 + T - 1) / T;
        k_agg2_final<<<blocks, T>>>(bufA, bufB, out, N);
    }
}